// round 3
// baseline (speedup 1.0000x reference)
#include <cuda_runtime.h>

// ---------------------------------------------------------------------------
// SO3Conv: out[b,g,off_l+v*d+m] = sum_{f,u} x[b,f,off_l+u*d+m] * W_l[f,g,u,v]
// where W_l[f,g,u,v] = (1/(64*sqrt(d))) * sum_n D[n, off_l+u*d+v] * w[f,g,n]
// Folding m into the row dim: per l a single GEMM M=1024d, K=64d, N=64d.
// ---------------------------------------------------------------------------

constexpr int IRREP = 455;

__host__ __device__ constexpr int OFF_OF(int l) {
    int s = 0;
    for (int i = 0; i < l; ++i) s += (2 * i + 1) * (2 * i + 1);
    return s;
}

// Scratch (static device globals; allocation-free kernel_launch).
__device__ __align__(256) float g_W[4096 * IRREP];    // per-l packed B operand
__device__ __align__(256) float g_A[65536 * IRREP];   // per-l packed A operand
__device__ __align__(256) float g_C[65536 * IRREP];   // per-l packed C result

__constant__ int   c_offs[8]  = {0, 1, 10, 35, 84, 165, 286, 455};
__constant__ float c_scale[7] = {
    0.015625f,                 // 1/(64*sqrt(1))
    0.0090210979560879045f,    // 1/(64*sqrt(3))
    0.0069877124296868430f,    // 1/(64*sqrt(5))
    0.0059056941504209480f,    // 1/(64*sqrt(7))
    0.0052083333333333333f,    // 1/(64*sqrt(9))
    0.0047111042269238420f,    // 1/(64*sqrt(11))
    0.0043336678140363560f     // 1/(64*sqrt(13))
};

// ---------------------------------------------------------------------------
// Kernel 1: psi GEMM (4096 x 455, K=64) with scatter into per-l W layout.
// Grid: (ceil(455/64)=8, 4096/64=64), 256 threads.
// ---------------------------------------------------------------------------
__global__ __launch_bounds__(256) void build_w_kernel(
    const float* __restrict__ Dm,   // (64, 455)
    const float* __restrict__ w)    // (64, 64, 64) viewed as (4096, 64)
{
    __shared__ __align__(16) float Ws[64][68];  // [n][fg_local]  (transposed w tile)
    __shared__ __align__(16) float Ds[64][64];  // [n][i_local]

    const int tid = threadIdx.x;
    const int i0  = blockIdx.x * 64;
    const int fg0 = blockIdx.y * 64;

    // load w tile (64 fg x 64 n), store transposed
#pragma unroll
    for (int it = 0; it < 4; ++it) {
        int idx = tid + it * 256;            // float4 index, 0..1023
        int r   = idx >> 4;                  // fg row 0..63
        int c4  = idx & 15;
        float4 v = *(const float4*)(w + (fg0 + r) * 64 + c4 * 4);
        Ws[c4 * 4 + 0][r] = v.x; Ws[c4 * 4 + 1][r] = v.y;
        Ws[c4 * 4 + 2][r] = v.z; Ws[c4 * 4 + 3][r] = v.w;
    }
    // load D tile (64 n x 64 i), guarded on i
#pragma unroll
    for (int it = 0; it < 16; ++it) {
        int idx = tid + it * 256;            // 0..4095
        int n   = idx >> 6;
        int c   = idx & 63;
        int gi  = i0 + c;
        Ds[n][c] = (gi < IRREP) ? Dm[n * IRREP + gi] : 0.f;
    }
    __syncthreads();

    const int tx = tid & 15, ty = tid >> 4;
    float acc[4][4] = {};
#pragma unroll
    for (int n = 0; n < 64; ++n) {
        float a[4], b[4];
        *(float4*)a = *(const float4*)(&Ws[n][ty * 4]);
        *(float4*)b = *(const float4*)(&Ds[n][tx * 4]);
#pragma unroll
        for (int ii = 0; ii < 4; ++ii)
#pragma unroll
            for (int jj = 0; jj < 4; ++jj)
                acc[ii][jj] += a[ii] * b[jj];
    }

    // scatter into per-l packed layout W_l[(f*d+u)*(64d) + g*d+v]
#pragma unroll
    for (int ii = 0; ii < 4; ++ii) {
        int fg = fg0 + ty * 4 + ii;
        int f = fg >> 6, g = fg & 63;
#pragma unroll
        for (int jj = 0; jj < 4; ++jj) {
            int gi = i0 + tx * 4 + jj;
            if (gi >= IRREP) continue;
            int l = 0;
#pragma unroll
            for (int t = 1; t <= 6; ++t) l += (gi >= c_offs[t]);
            int d  = 2 * l + 1;
            int j2 = gi - c_offs[l];
            int u  = j2 / d;
            int v  = j2 - u * d;
            g_W[c_offs[l] * 4096 + (f * d + u) * (64 * d) + g * d + v] =
                acc[ii][jj] * c_scale[l];
        }
    }
}

// ---------------------------------------------------------------------------
// Kernel 2: pack x into per-l A operand. Block = one batch index b.
// Reads coalesced per-f segments; writes full contiguous A rows.
// ---------------------------------------------------------------------------
template <int L>
__global__ __launch_bounds__(256) void pack_kernel(const float* __restrict__ x)
{
    constexpr int DL = 2 * L + 1, D2 = DL * DL, KN = 64 * DL;
    constexpr int OFF = OFF_OF(L), AOFF = 65536 * OFF;
    __shared__ float sx[64 * D2];

    const int b = blockIdx.x, tid = threadIdx.x;
    for (int idx = tid; idx < 64 * D2; idx += 256) {
        int f = idx / D2, j = idx - f * D2;
        sx[idx] = x[(b * 64 + f) * IRREP + OFF + j];
    }
    __syncthreads();
    for (int idx = tid; idx < DL * KN; idx += 256) {
        int m = idx / KN, t = idx - m * KN;
        int f = t / DL, u = t - f * DL;
        g_A[AOFF + (b * DL + m) * KN + t] = sx[f * D2 + u * DL + m];
    }
}

// ---------------------------------------------------------------------------
// Kernel 3: fp32 SIMT GEMM. BM=128, BN=64, BK=16, 256 threads, 8x4 per thread.
// M = 1024*DL (multiple of 128), N = K = 64*DL.
// ---------------------------------------------------------------------------
template <int L>
__global__ __launch_bounds__(256) void gemm_kernel()
{
    constexpr int DL = 2 * L + 1, KN = 64 * DL;
    constexpr int OFF = OFF_OF(L), AOFF = 65536 * OFF, WOFF = 4096 * OFF;
    const float* __restrict__ A = g_A + AOFF;
    const float* __restrict__ B = g_W + WOFF;
    float* __restrict__ C       = g_C + AOFF;

    __shared__ __align__(16) float As[16][128];  // [k][m] transposed
    __shared__ __align__(16) float Bs[16][64];   // [k][n]

    const int tid = threadIdx.x;
    const int tx = tid & 15, ty = tid >> 4;
    const int n0 = blockIdx.x * 64;
    const int m0 = blockIdx.y * 128;

    float acc[8][4] = {};
    for (int k0 = 0; k0 < KN; k0 += 16) {
#pragma unroll
        for (int it = 0; it < 2; ++it) {
            int idx = tid + it * 256;        // float4 index 0..511
            int r = idx >> 2, c4 = idx & 3;
            float4 v = *(const float4*)(A + (m0 + r) * KN + k0 + c4 * 4);
            As[c4 * 4 + 0][r] = v.x; As[c4 * 4 + 1][r] = v.y;
            As[c4 * 4 + 2][r] = v.z; As[c4 * 4 + 3][r] = v.w;
        }
        {
            int r = tid >> 4, c4 = tid & 15;
            *(float4*)(&Bs[r][c4 * 4]) =
                *(const float4*)(B + (k0 + r) * KN + n0 + c4 * 4);
        }
        __syncthreads();
#pragma unroll
        for (int kk = 0; kk < 16; ++kk) {
            float a[8], bb[4];
            *(float4*)(a)     = *(const float4*)(&As[kk][ty * 8]);
            *(float4*)(a + 4) = *(const float4*)(&As[kk][ty * 8 + 4]);
            *(float4*)(bb)    = *(const float4*)(&Bs[kk][tx * 4]);
#pragma unroll
            for (int i = 0; i < 8; ++i)
#pragma unroll
                for (int j = 0; j < 4; ++j)
                    acc[i][j] += a[i] * bb[j];
        }
        __syncthreads();
    }
#pragma unroll
    for (int i = 0; i < 8; ++i) {
        int row = m0 + ty * 8 + i;
        *(float4*)(C + row * KN + n0 + tx * 4) = *(float4*)(acc[i]);
    }
}

// ---------------------------------------------------------------------------
// Kernel 4: unpack C back into (B, 64, 455) output layout.
// ---------------------------------------------------------------------------
template <int L>
__global__ __launch_bounds__(256) void unpack_kernel(float* __restrict__ out)
{
    constexpr int DL = 2 * L + 1, D2 = DL * DL, KN = 64 * DL;
    constexpr int OFF = OFF_OF(L), AOFF = 65536 * OFF;
    __shared__ float sc[DL * (KN + 1)];   // +1 pad: conflict-free transposed reads

    const int b = blockIdx.x, tid = threadIdx.x;
    for (int idx = tid; idx < DL * KN; idx += 256) {
        int m = idx / KN, c = idx - m * KN;
        sc[m * (KN + 1) + c] = g_C[AOFF + (b * DL + m) * KN + c];
    }
    __syncthreads();
    for (int idx = tid; idx < 64 * D2; idx += 256) {
        int g = idx / D2, j = idx - g * D2;
        int v = j / DL, m = j - v * DL;
        out[(b * 64 + g) * IRREP + OFF + j] = sc[m * (KN + 1) + g * DL + v];
    }
}

// ---------------------------------------------------------------------------
extern "C" void kernel_launch(void* const* d_in, const int* in_sizes, int n_in,
                              void* d_out, int out_size)
{
    const float* x  = (const float*)d_in[0];   // (1024, 64, 455)
    const float* Dm = (const float*)d_in[1];   // (64, 455)
    const float* w  = (const float*)d_in[2];   // (64, 64, 64)
    float* out = (float*)d_out;                // (1024, 64, 455)

    build_w_kernel<<<dim3(8, 64), 256>>>(Dm, w);

#define RUN_L(L)                                                        \
    pack_kernel<L><<<1024, 256>>>(x);                                   \
    gemm_kernel<L><<<dim3(2 * L + 1, 8 * (2 * L + 1)), 256>>>();        \
    unpack_kernel<L><<<1024, 256>>>(out);

    RUN_L(0)
    RUN_L(1)
    RUN_L(2)
    RUN_L(3)
    RUN_L(4)
    RUN_L(5)
    RUN_L(6)
#undef RUN_L
}

// round 10
// speedup vs baseline: 1.7404x; 1.7404x over previous
#include <cuda_runtime.h>
#include <cuda_bf16.h>
#include <cstdint>

// ---------------------------------------------------------------------------
// SO3Conv via per-degree GEMMs on mma.sync (bf16 hi/lo split, fp32 accum).
//   C[(b,m),(g,v)] = sum_{(f,u)} A[(b,m),(f,u)] * Bt[(g,v),(f,u)]
//   per l: M=1024d, N=K=64d.  (tcgen05 is rejected by the harness's
//   compute_103 PTX target, so we use the arch-stable HMMA path.)
// ---------------------------------------------------------------------------

constexpr int IRREP = 455;

__host__ __device__ constexpr int OFF_OF(int l) {
    int s = 0;
    for (int i = 0; i < l; ++i) s += (2 * i + 1) * (2 * i + 1);
    return s;
}

// Scratch (static device globals; allocation-free kernel_launch).
__device__ __align__(256) __nv_bfloat16 g_Ahi[65536L * IRREP];
__device__ __align__(256) __nv_bfloat16 g_Alo[65536L * IRREP];
__device__ __align__(256) __nv_bfloat16 g_Bhi[4096 * IRREP];
__device__ __align__(256) __nv_bfloat16 g_Blo[4096 * IRREP];
__device__ __align__(256) float         g_C[65536L * IRREP];

__constant__ int   c_offs[8]  = {0, 1, 10, 35, 84, 165, 286, 455};
__constant__ float c_scale[7] = {
    0.015625f, 0.0090210979560879045f, 0.0069877124296868430f,
    0.0059056941504209480f, 0.0052083333333333333f,
    0.0047111042269238420f, 0.0043336678140363560f
};

__device__ __forceinline__ uint32_t su32(const void* p) {
    uint32_t a;
    asm("{ .reg .u64 t; cvta.to.shared.u64 t, %1; cvt.u32.u64 %0, t; }"
        : "=r"(a) : "l"(p));
    return a;
}

__device__ __forceinline__ void ldsm4(uint32_t& r0, uint32_t& r1,
                                      uint32_t& r2, uint32_t& r3, uint32_t a) {
    asm volatile("ldmatrix.sync.aligned.m8n8.x4.shared.b16 {%0,%1,%2,%3}, [%4];"
                 : "=r"(r0), "=r"(r1), "=r"(r2), "=r"(r3) : "r"(a));
}

__device__ __forceinline__ void mma16816(float* c, const uint32_t* a,
                                         const uint32_t* b) {
    asm volatile(
        "mma.sync.aligned.m16n8k16.row.col.f32.bf16.bf16.f32 "
        "{%0,%1,%2,%3}, {%4,%5,%6,%7}, {%8,%9}, {%0,%1,%2,%3};"
        : "+f"(c[0]), "+f"(c[1]), "+f"(c[2]), "+f"(c[3])
        : "r"(a[0]), "r"(a[1]), "r"(a[2]), "r"(a[3]), "r"(b[0]), "r"(b[1]));
}

__device__ __forceinline__ void split_bf16(float v, __nv_bfloat16& h, __nv_bfloat16& l) {
    h = __float2bfloat16(v);
    l = __float2bfloat16(v - __bfloat162float(h));
}

// ---------------------------------------------------------------------------
// Kernel 1: psi GEMM (4096 x 455, K=64) -> scatter transposed bf16 hi/lo B.
//   Bt_l[(g*d+v)][(f*d+u)] = psi[f,g,u,v] * scale_l
// ---------------------------------------------------------------------------
__global__ __launch_bounds__(256) void build_w_kernel(
    const float* __restrict__ Dm,   // (64, 455)
    const float* __restrict__ w)    // (4096, 64)
{
    __shared__ __align__(16) float Ws[64][68];
    __shared__ __align__(16) float Ds[64][64];

    const int tid = threadIdx.x;
    const int i0  = blockIdx.x * 64;
    const int fg0 = blockIdx.y * 64;

#pragma unroll
    for (int it = 0; it < 4; ++it) {
        int idx = tid + it * 256;
        int r   = idx >> 4;
        int c4  = idx & 15;
        float4 v = *(const float4*)(w + (fg0 + r) * 64 + c4 * 4);
        Ws[c4 * 4 + 0][r] = v.x; Ws[c4 * 4 + 1][r] = v.y;
        Ws[c4 * 4 + 2][r] = v.z; Ws[c4 * 4 + 3][r] = v.w;
    }
#pragma unroll
    for (int it = 0; it < 16; ++it) {
        int idx = tid + it * 256;
        int n   = idx >> 6;
        int c   = idx & 63;
        int gi  = i0 + c;
        Ds[n][c] = (gi < IRREP) ? Dm[n * IRREP + gi] : 0.f;
    }
    __syncthreads();

    const int tx = tid & 15, ty = tid >> 4;
    float acc[4][4] = {};
#pragma unroll
    for (int n = 0; n < 64; ++n) {
        float a[4], b[4];
        *(float4*)a = *(const float4*)(&Ws[n][ty * 4]);
        *(float4*)b = *(const float4*)(&Ds[n][tx * 4]);
#pragma unroll
        for (int ii = 0; ii < 4; ++ii)
#pragma unroll
            for (int jj = 0; jj < 4; ++jj)
                acc[ii][jj] += a[ii] * b[jj];
    }

#pragma unroll
    for (int ii = 0; ii < 4; ++ii) {
        int fg = fg0 + ty * 4 + ii;
        int f = fg >> 6, g = fg & 63;
#pragma unroll
        for (int jj = 0; jj < 4; ++jj) {
            int gi = i0 + tx * 4 + jj;
            if (gi >= IRREP) continue;
            int l = 0;
#pragma unroll
            for (int t = 1; t <= 6; ++t) l += (gi >= c_offs[t]);
            int d  = 2 * l + 1;
            int j2 = gi - c_offs[l];
            int u  = j2 / d;
            int v  = j2 - u * d;
            float val = acc[ii][jj] * c_scale[l];
            __nv_bfloat16 h, lo;
            split_bf16(val, h, lo);
            long bi = (long)c_offs[l] * 4096 + (long)(g * d + v) * (64 * d) + (f * d + u);
            g_Bhi[bi] = h;
            g_Blo[bi] = lo;
        }
    }
}

// ---------------------------------------------------------------------------
// Kernel 2: pack x into per-l A operand (bf16 hi/lo), A[(b*d+m)][(f*d+u)].
// ---------------------------------------------------------------------------
template <int L>
__global__ __launch_bounds__(256) void pack_kernel(const float* __restrict__ x)
{
    constexpr int DL = 2 * L + 1, D2 = DL * DL, KN = 64 * DL;
    constexpr int OFF = OFF_OF(L);
    constexpr long AOFF = 65536L * OFF;
    __shared__ float sx[64 * D2];

    const int b = blockIdx.x, tid = threadIdx.x;
    for (int idx = tid; idx < 64 * D2; idx += 256) {
        int f = idx / D2, j = idx - f * D2;
        sx[idx] = x[(b * 64 + f) * IRREP + OFF + j];
    }
    __syncthreads();
    for (int idx = tid; idx < DL * KN; idx += 256) {
        int m = idx / KN, t = idx - m * KN;
        int f = t / DL, u = t - f * DL;
        float v = sx[f * D2 + u * DL + m];
        __nv_bfloat16 h, lo;
        split_bf16(v, h, lo);
        long ai = AOFF + (long)(b * DL + m) * KN + t;
        g_Ahi[ai] = h;
        g_Alo[ai] = lo;
    }
}

// ---------------------------------------------------------------------------
// Kernel 3: HMMA GEMM. CTA tile 128x64xK32, 256 threads, warp grid 4Mx2N,
// warp tile 32x32. Split precision: D += Ah*Bh^T + Ah*Bl^T + Al*Bh^T.
// smem rows padded to 40 bf16 (80B): conflict-free stores and ldmatrix.
// ---------------------------------------------------------------------------
template <int L>
__global__ __launch_bounds__(256) void mma_gemm_kernel()
{
    constexpr int DL = 2 * L + 1, KN = 64 * DL, NCH = 2 * DL;
    constexpr int OFF = OFF_OF(L);
    constexpr long AOFF = 65536L * OFF;
    constexpr int  BOFF = 4096 * OFF;

    const __nv_bfloat16* __restrict__ Ah = g_Ahi + AOFF;
    const __nv_bfloat16* __restrict__ Al = g_Alo + AOFF;
    const __nv_bfloat16* __restrict__ Bh = g_Bhi + BOFF;
    const __nv_bfloat16* __restrict__ Bl = g_Blo + BOFF;
    float* __restrict__ C = g_C + AOFF;

    __shared__ __align__(16) __nv_bfloat16 sAh[128 * 40];
    __shared__ __align__(16) __nv_bfloat16 sAl[128 * 40];
    __shared__ __align__(16) __nv_bfloat16 sBh[64 * 40];
    __shared__ __align__(16) __nv_bfloat16 sBl[64 * 40];

    const int tid  = threadIdx.x;
    const int wid  = tid >> 5;
    const int lane = tid & 31;
    const int n0   = blockIdx.x * 64;
    const int m0   = blockIdx.y * 128;
    const int mb   = (wid & 3) * 32;   // warp M offset in CTA tile
    const int nb   = (wid >> 2) * 32;  // warp N offset

    const uint32_t bAh = su32(sAh), bAl = su32(sAl);
    const uint32_t bBh = su32(sBh), bBl = su32(sBl);

    // ldmatrix lane-address components (in elements).
    const int aRow = ((lane >> 3) & 1) * 8 + (lane & 7);   // + mi*16 + mb
    const int aCol = (lane >> 4) * 8;                      // + kk
    const int bRow = (lane >> 4) * 8 + (lane & 7);         // + j*16 + nb
    const int bCol = ((lane >> 3) & 1) * 8;                // + kk

    float acc[2][4][4] = {};

    for (int c = 0; c < NCH; ++c) {
        const int k0 = c * 32;
        // ---- stage chunk into smem ----
#pragma unroll
        for (int i = 0; i < 2; ++i) {
            int idx = tid + i * 256;        // 0..511
            int r = idx >> 2, q = idx & 3;  // row, 8-elem quad
            long go = (long)(m0 + r) * KN + k0 + q * 8;
            *(uint4*)(sAh + r * 40 + q * 8) = *(const uint4*)(Ah + go);
            *(uint4*)(sAl + r * 40 + q * 8) = *(const uint4*)(Al + go);
        }
        {
            int r = tid >> 2, q = tid & 3;
            long go = (long)(n0 + r) * KN + k0 + q * 8;
            *(uint4*)(sBh + r * 40 + q * 8) = *(const uint4*)(Bh + go);
            *(uint4*)(sBl + r * 40 + q * 8) = *(const uint4*)(Bl + go);
        }
        __syncthreads();

        // ---- compute ----
#pragma unroll
        for (int kk = 0; kk < 32; kk += 16) {
            uint32_t ah[2][4], al[2][4], bh[2][4], bl[2][4];
#pragma unroll
            for (int mi = 0; mi < 2; ++mi) {
                uint32_t off = ((mb + mi * 16 + aRow) * 40 + kk + aCol) * 2;
                ldsm4(ah[mi][0], ah[mi][1], ah[mi][2], ah[mi][3], bAh + off);
                ldsm4(al[mi][0], al[mi][1], al[mi][2], al[mi][3], bAl + off);
            }
#pragma unroll
            for (int j = 0; j < 2; ++j) {
                uint32_t off = ((nb + j * 16 + bRow) * 40 + kk + bCol) * 2;
                ldsm4(bh[j][0], bh[j][1], bh[j][2], bh[j][3], bBh + off);
                ldsm4(bl[j][0], bl[j][1], bl[j][2], bl[j][3], bBl + off);
            }
#pragma unroll
            for (int mi = 0; mi < 2; ++mi)
#pragma unroll
                for (int j = 0; j < 2; ++j)
#pragma unroll
                    for (int t = 0; t < 2; ++t) {
                        float* cc = acc[mi][j * 2 + t];
                        mma16816(cc, ah[mi], &bh[j][2 * t]);
                        mma16816(cc, ah[mi], &bl[j][2 * t]);
                        mma16816(cc, al[mi], &bh[j][2 * t]);
                    }
        }
        __syncthreads();
    }

    // ---- epilogue: fragment -> g_C ----
#pragma unroll
    for (int mi = 0; mi < 2; ++mi) {
        long row = m0 + mb + mi * 16 + (lane >> 2);
#pragma unroll
        for (int n = 0; n < 4; ++n) {
            long col = n0 + nb + n * 8 + (lane & 3) * 2;
            *(float2*)(C + row * KN + col) =
                make_float2(acc[mi][n][0], acc[mi][n][1]);
            *(float2*)(C + (row + 8) * KN + col) =
                make_float2(acc[mi][n][2], acc[mi][n][3]);
        }
    }
}

// ---------------------------------------------------------------------------
// Kernel 4: unpack C back into (B, 64, 455) output layout.
// ---------------------------------------------------------------------------
template <int L>
__global__ __launch_bounds__(256) void unpack_kernel(float* __restrict__ out)
{
    constexpr int DL = 2 * L + 1, D2 = DL * DL, KN = 64 * DL;
    constexpr int OFF = OFF_OF(L);
    constexpr long AOFF = 65536L * OFF;
    __shared__ float sc[DL * (KN + 1)];

    const int b = blockIdx.x, tid = threadIdx.x;
    for (int idx = tid; idx < DL * KN; idx += 256) {
        int m = idx / KN, c = idx - m * KN;
        sc[m * (KN + 1) + c] = g_C[AOFF + (long)(b * DL + m) * KN + c];
    }
    __syncthreads();
    for (int idx = tid; idx < 64 * D2; idx += 256) {
        int g = idx / D2, j = idx - g * D2;
        int v = j / DL, m = j - v * DL;
        out[(b * 64 + g) * IRREP + OFF + j] = sc[m * (KN + 1) + g * DL + v];
    }
}

// ---------------------------------------------------------------------------
extern "C" void kernel_launch(void* const* d_in, const int* in_sizes, int n_in,
                              void* d_out, int out_size)
{
    const float* x  = (const float*)d_in[0];   // (1024, 64, 455)
    const float* Dm = (const float*)d_in[1];   // (64, 455)
    const float* w  = (const float*)d_in[2];   // (64, 64, 64)
    float* out = (float*)d_out;                // (1024, 64, 455)

    build_w_kernel<<<dim3(8, 64), 256>>>(Dm, w);

#define RUN_L(L)                                                            \
    pack_kernel<L><<<1024, 256>>>(x);                                       \
    mma_gemm_kernel<L><<<dim3(2 * L + 1, 8 * (2 * L + 1)), 256>>>();        \
    unpack_kernel<L><<<1024, 256>>>(out);

    RUN_L(0)
    RUN_L(1)
    RUN_L(2)
    RUN_L(3)
    RUN_L(4)
    RUN_L(5)
    RUN_L(6)
#undef RUN_L
}

// round 14
// speedup vs baseline: 1.8299x; 1.0514x over previous
#include <cuda_runtime.h>
#include <cuda_bf16.h>
#include <cstdint>

// ---------------------------------------------------------------------------
// SO3Conv via per-degree GEMMs on mma.sync (bf16 hi/lo split, fp32 accum).
//   C[(b,m),(g,v)] = sum_{(f,u)} A[(b,m),(f,u)] * Bt[(g,v),(f,u)]
//   per l: M=1024d, N=K=64d.
// R11: cp.async double-buffered smem pipeline in the GEMM.
// ---------------------------------------------------------------------------

constexpr int IRREP = 455;

__host__ __device__ constexpr int OFF_OF(int l) {
    int s = 0;
    for (int i = 0; i < l; ++i) s += (2 * i + 1) * (2 * i + 1);
    return s;
}

__device__ __align__(256) __nv_bfloat16 g_Ahi[65536L * IRREP];
__device__ __align__(256) __nv_bfloat16 g_Alo[65536L * IRREP];
__device__ __align__(256) __nv_bfloat16 g_Bhi[4096 * IRREP];
__device__ __align__(256) __nv_bfloat16 g_Blo[4096 * IRREP];
__device__ __align__(256) float         g_C[65536L * IRREP];

__constant__ int   c_offs[8]  = {0, 1, 10, 35, 84, 165, 286, 455};
__constant__ float c_scale[7] = {
    0.015625f, 0.0090210979560879045f, 0.0069877124296868430f,
    0.0059056941504209480f, 0.0052083333333333333f,
    0.0047111042269238420f, 0.0043336678140363560f
};

__device__ __forceinline__ uint32_t su32(const void* p) {
    uint32_t a;
    asm("{ .reg .u64 t; cvta.to.shared.u64 t, %1; cvt.u32.u64 %0, t; }"
        : "=r"(a) : "l"(p));
    return a;
}

__device__ __forceinline__ void ldsm4(uint32_t& r0, uint32_t& r1,
                                      uint32_t& r2, uint32_t& r3, uint32_t a) {
    asm volatile("ldmatrix.sync.aligned.m8n8.x4.shared.b16 {%0,%1,%2,%3}, [%4];"
                 : "=r"(r0), "=r"(r1), "=r"(r2), "=r"(r3) : "r"(a));
}

__device__ __forceinline__ void mma16816(float* c, const uint32_t* a,
                                         const uint32_t* b) {
    asm volatile(
        "mma.sync.aligned.m16n8k16.row.col.f32.bf16.bf16.f32 "
        "{%0,%1,%2,%3}, {%4,%5,%6,%7}, {%8,%9}, {%0,%1,%2,%3};"
        : "+f"(c[0]), "+f"(c[1]), "+f"(c[2]), "+f"(c[3])
        : "r"(a[0]), "r"(a[1]), "r"(a[2]), "r"(a[3]), "r"(b[0]), "r"(b[1]));
}

#define CP16(s, g) \
    asm volatile("cp.async.cg.shared.global [%0], [%1], 16;" :: "r"(s), "l"(g))
#define CP_COMMIT() asm volatile("cp.async.commit_group;" ::: "memory")
#define CP_WAIT(N)  asm volatile("cp.async.wait_group %0;" :: "n"(N) : "memory")

__device__ __forceinline__ void split_bf16(float v, __nv_bfloat16& h, __nv_bfloat16& l) {
    h = __float2bfloat16(v);
    l = __float2bfloat16(v - __bfloat162float(h));
}

// ---------------------------------------------------------------------------
// Kernel 1: psi GEMM (4096 x 455, K=64) -> scatter transposed bf16 hi/lo B.
// ---------------------------------------------------------------------------
__global__ __launch_bounds__(256) void build_w_kernel(
    const float* __restrict__ Dm,   // (64, 455)
    const float* __restrict__ w)    // (4096, 64)
{
    __shared__ __align__(16) float Ws[64][68];
    __shared__ __align__(16) float Ds[64][64];

    const int tid = threadIdx.x;
    const int i0  = blockIdx.x * 64;
    const int fg0 = blockIdx.y * 64;

#pragma unroll
    for (int it = 0; it < 4; ++it) {
        int idx = tid + it * 256;
        int r   = idx >> 4;
        int c4  = idx & 15;
        float4 v = *(const float4*)(w + (fg0 + r) * 64 + c4 * 4);
        Ws[c4 * 4 + 0][r] = v.x; Ws[c4 * 4 + 1][r] = v.y;
        Ws[c4 * 4 + 2][r] = v.z; Ws[c4 * 4 + 3][r] = v.w;
    }
#pragma unroll
    for (int it = 0; it < 16; ++it) {
        int idx = tid + it * 256;
        int n   = idx >> 6;
        int c   = idx & 63;
        int gi  = i0 + c;
        Ds[n][c] = (gi < IRREP) ? Dm[n * IRREP + gi] : 0.f;
    }
    __syncthreads();

    const int tx = tid & 15, ty = tid >> 4;
    float acc[4][4] = {};
#pragma unroll
    for (int n = 0; n < 64; ++n) {
        float a[4], b[4];
        *(float4*)a = *(const float4*)(&Ws[n][ty * 4]);
        *(float4*)b = *(const float4*)(&Ds[n][tx * 4]);
#pragma unroll
        for (int ii = 0; ii < 4; ++ii)
#pragma unroll
            for (int jj = 0; jj < 4; ++jj)
                acc[ii][jj] += a[ii] * b[jj];
    }

#pragma unroll
    for (int ii = 0; ii < 4; ++ii) {
        int fg = fg0 + ty * 4 + ii;
        int f = fg >> 6, g = fg & 63;
#pragma unroll
        for (int jj = 0; jj < 4; ++jj) {
            int gi = i0 + tx * 4 + jj;
            if (gi >= IRREP) continue;
            int l = 0;
#pragma unroll
            for (int t = 1; t <= 6; ++t) l += (gi >= c_offs[t]);
            int d  = 2 * l + 1;
            int j2 = gi - c_offs[l];
            int u  = j2 / d;
            int v  = j2 - u * d;
            float val = acc[ii][jj] * c_scale[l];
            __nv_bfloat16 h, lo;
            split_bf16(val, h, lo);
            long bi = (long)c_offs[l] * 4096 + (long)(g * d + v) * (64 * d) + (f * d + u);
            g_Bhi[bi] = h;
            g_Blo[bi] = lo;
        }
    }
}

// ---------------------------------------------------------------------------
// Kernel 2: pack x into per-l A operand (bf16 hi/lo), A[(b*d+m)][(f*d+u)].
// ---------------------------------------------------------------------------
template <int L>
__global__ __launch_bounds__(256) void pack_kernel(const float* __restrict__ x)
{
    constexpr int DL = 2 * L + 1, D2 = DL * DL, KN = 64 * DL;
    constexpr int OFF = OFF_OF(L);
    constexpr long AOFF = 65536L * OFF;
    __shared__ float sx[64 * D2];

    const int b = blockIdx.x, tid = threadIdx.x;
    for (int idx = tid; idx < 64 * D2; idx += 256) {
        int f = idx / D2, j = idx - f * D2;
        sx[idx] = x[(b * 64 + f) * IRREP + OFF + j];
    }
    __syncthreads();
    for (int idx = tid; idx < DL * KN; idx += 256) {
        int m = idx / KN, t = idx - m * KN;
        int f = t / DL, u = t - f * DL;
        float v = sx[f * D2 + u * DL + m];
        __nv_bfloat16 h, lo;
        split_bf16(v, h, lo);
        long ai = AOFF + (long)(b * DL + m) * KN + t;
        g_Ahi[ai] = h;
        g_Alo[ai] = lo;
    }
}

// ---------------------------------------------------------------------------
// Kernel 3: HMMA GEMM, cp.async double-buffered.
// CTA tile 128x64xK32, 256 threads, warp grid 4Mx2N, warp tile 32x32.
// D += Ah*Bh^T + Ah*Bl^T + Al*Bh^T.
// Stage layout (bytes, rows padded to 40 bf16 = 80B):
//   Ah @ 0      (10240) | Al @ 10240 (10240) | Bh @ 20480 (5120) | Bl @ 25600 (5120)
// STAGE = 30720, 2 stages = 61440 dynamic smem.
// ---------------------------------------------------------------------------
constexpr int GS_OAH = 0, GS_OAL = 10240, GS_OBH = 20480, GS_OBL = 25600;
constexpr int GS_STAGE = 30720;
constexpr int GEMM_DSMEM = 2 * GS_STAGE;

template <int L>
__global__ __launch_bounds__(256) void mma_gemm_kernel()
{
    constexpr int DL = 2 * L + 1, KN = 64 * DL, NCH = 2 * DL;
    constexpr int OFF = OFF_OF(L);
    constexpr long AOFF = 65536L * OFF;
    constexpr int  BOFF = 4096 * OFF;

    const __nv_bfloat16* __restrict__ Ah = g_Ahi + AOFF;
    const __nv_bfloat16* __restrict__ Al = g_Alo + AOFF;
    const __nv_bfloat16* __restrict__ Bh = g_Bhi + BOFF;
    const __nv_bfloat16* __restrict__ Bl = g_Blo + BOFF;
    float* __restrict__ C = g_C + AOFF;

    extern __shared__ __align__(128) char smem[];
    const uint32_t sbase = su32(smem);

    const int tid  = threadIdx.x;
    const int wid  = tid >> 5;
    const int lane = tid & 31;
    const int n0   = blockIdx.x * 64;
    const int m0   = blockIdx.y * 128;
    const int mb   = (wid & 3) * 32;
    const int nb   = (wid >> 2) * 32;

    // ldmatrix lane-address components (elements).
    const int aRow = ((lane >> 3) & 1) * 8 + (lane & 7);
    const int aCol = (lane >> 4) * 8;
    const int bRow = (lane >> 4) * 8 + (lane & 7);
    const int bCol = ((lane >> 3) & 1) * 8;

    float acc[2][4][4] = {};

    auto issue_stage = [&](int c, int s) {
        const int k0 = c * 32;
        const uint32_t sb = sbase + s * GS_STAGE;
#pragma unroll
        for (int i = 0; i < 2; ++i) {
            int idx = tid + i * 256;          // 0..511
            int r = idx >> 2, q = idx & 3;
            long go = (long)(m0 + r) * KN + k0 + q * 8;
            uint32_t so = (uint32_t)(r * 80 + q * 16);
            CP16(sb + GS_OAH + so, (const char*)Ah + go * 2);
            CP16(sb + GS_OAL + so, (const char*)Al + go * 2);
        }
        {
            int r = tid >> 2, q = tid & 3;
            long go = (long)(n0 + r) * KN + k0 + q * 8;
            uint32_t so = (uint32_t)(r * 80 + q * 16);
            CP16(sb + GS_OBH + so, (const char*)Bh + go * 2);
            CP16(sb + GS_OBL + so, (const char*)Bl + go * 2);
        }
        CP_COMMIT();
    };

    issue_stage(0, 0);

    for (int c = 0; c < NCH; ++c) {
        const int s = c & 1;
        if (c + 1 < NCH) {
            issue_stage(c + 1, s ^ 1);
            CP_WAIT(1);                       // stage c complete
        } else {
            CP_WAIT(0);
        }
        __syncthreads();

        const uint32_t sb  = sbase + s * GS_STAGE;
        const uint32_t bAh = sb + GS_OAH, bAl = sb + GS_OAL;
        const uint32_t bBh = sb + GS_OBH, bBl = sb + GS_OBL;

#pragma unroll
        for (int kk = 0; kk < 32; kk += 16) {
            uint32_t ah[2][4], al[2][4], bh[2][4], bl[2][4];
#pragma unroll
            for (int mi = 0; mi < 2; ++mi) {
                uint32_t off = ((mb + mi * 16 + aRow) * 40 + kk + aCol) * 2;
                ldsm4(ah[mi][0], ah[mi][1], ah[mi][2], ah[mi][3], bAh + off);
                ldsm4(al[mi][0], al[mi][1], al[mi][2], al[mi][3], bAl + off);
            }
#pragma unroll
            for (int j = 0; j < 2; ++j) {
                uint32_t off = ((nb + j * 16 + bRow) * 40 + kk + bCol) * 2;
                ldsm4(bh[j][0], bh[j][1], bh[j][2], bh[j][3], bBh + off);
                ldsm4(bl[j][0], bl[j][1], bl[j][2], bl[j][3], bBl + off);
            }
#pragma unroll
            for (int mi = 0; mi < 2; ++mi)
#pragma unroll
                for (int j = 0; j < 2; ++j)
#pragma unroll
                    for (int t = 0; t < 2; ++t) {
                        float* cc = acc[mi][j * 2 + t];
                        mma16816(cc, ah[mi], &bh[j][2 * t]);
                        mma16816(cc, ah[mi], &bl[j][2 * t]);
                        mma16816(cc, al[mi], &bh[j][2 * t]);
                    }
        }
        __syncthreads();
    }

    // ---- epilogue: fragment -> g_C ----
#pragma unroll
    for (int mi = 0; mi < 2; ++mi) {
        long row = m0 + mb + mi * 16 + (lane >> 2);
#pragma unroll
        for (int n = 0; n < 4; ++n) {
            long col = n0 + nb + n * 8 + (lane & 3) * 2;
            *(float2*)(C + row * KN + col) =
                make_float2(acc[mi][n][0], acc[mi][n][1]);
            *(float2*)(C + (row + 8) * KN + col) =
                make_float2(acc[mi][n][2], acc[mi][n][3]);
        }
    }
}

// ---------------------------------------------------------------------------
// Kernel 4: unpack C back into (B, 64, 455) output layout.
// ---------------------------------------------------------------------------
template <int L>
__global__ __launch_bounds__(256) void unpack_kernel(float* __restrict__ out)
{
    constexpr int DL = 2 * L + 1, D2 = DL * DL, KN = 64 * DL;
    constexpr int OFF = OFF_OF(L);
    constexpr long AOFF = 65536L * OFF;
    __shared__ float sc[DL * (KN + 1)];

    const int b = blockIdx.x, tid = threadIdx.x;
    for (int idx = tid; idx < DL * KN; idx += 256) {
        int m = idx / KN, c = idx - m * KN;
        sc[m * (KN + 1) + c] = g_C[AOFF + (long)(b * DL + m) * KN + c];
    }
    __syncthreads();
    for (int idx = tid; idx < 64 * D2; idx += 256) {
        int g = idx / D2, j = idx - g * D2;
        int v = j / DL, m = j - v * DL;
        out[(b * 64 + g) * IRREP + OFF + j] = sc[m * (KN + 1) + g * DL + v];
    }
}

// ---------------------------------------------------------------------------
extern "C" void kernel_launch(void* const* d_in, const int* in_sizes, int n_in,
                              void* d_out, int out_size)
{
    const float* x  = (const float*)d_in[0];   // (1024, 64, 455)
    const float* Dm = (const float*)d_in[1];   // (64, 455)
    const float* w  = (const float*)d_in[2];   // (64, 64, 64)
    float* out = (float*)d_out;                // (1024, 64, 455)

    cudaFuncSetAttribute(mma_gemm_kernel<0>, cudaFuncAttributeMaxDynamicSharedMemorySize, GEMM_DSMEM);
    cudaFuncSetAttribute(mma_gemm_kernel<1>, cudaFuncAttributeMaxDynamicSharedMemorySize, GEMM_DSMEM);
    cudaFuncSetAttribute(mma_gemm_kernel<2>, cudaFuncAttributeMaxDynamicSharedMemorySize, GEMM_DSMEM);
    cudaFuncSetAttribute(mma_gemm_kernel<3>, cudaFuncAttributeMaxDynamicSharedMemorySize, GEMM_DSMEM);
    cudaFuncSetAttribute(mma_gemm_kernel<4>, cudaFuncAttributeMaxDynamicSharedMemorySize, GEMM_DSMEM);
    cudaFuncSetAttribute(mma_gemm_kernel<5>, cudaFuncAttributeMaxDynamicSharedMemorySize, GEMM_DSMEM);
    cudaFuncSetAttribute(mma_gemm_kernel<6>, cudaFuncAttributeMaxDynamicSharedMemorySize, GEMM_DSMEM);

    build_w_kernel<<<dim3(8, 64), 256>>>(Dm, w);

#define RUN_L(L)                                                              \
    pack_kernel<L><<<1024, 256>>>(x);                                         \
    mma_gemm_kernel<L><<<dim3(2 * L + 1, 8 * (2 * L + 1)), 256, GEMM_DSMEM>>>(); \
    unpack_kernel<L><<<1024, 256>>>(out);

    RUN_L(0)
    RUN_L(1)
    RUN_L(2)
    RUN_L(3)
    RUN_L(4)
    RUN_L(5)
    RUN_L(6)
#undef RUN_L
}